// round 16
// baseline (speedup 1.0000x reference)
#include <cuda_runtime.h>
#include <cuda_fp16.h>
#include <stdint.h>

// Two-kernel split (r12/r14/r15 wins), GEMM restructured for zero-wait
// pipelining + better wave balance:
//  1) gen_kernel: x -> A fp16 [32768, 2304] (silu + Cox-de-Boor bases).
//  2) gemm_kernel: out = A * Wt^T. CTA tile 64x256 (full N), 512 CTAs
//     (3.46 waves vs r15's 1.73 -> less quantization), 256 thr, 8 warps of
//     32x64 tiles. A AND B double-buffered (194.5KB), ONE combined cp.async
//     commit group per chunk issued TWO chunks ahead -> the per-chunk
//     wait_group retires an already-landed group (r15's single-buffered A
//     refill exposed a blocking transfer every chunk, ~50-70us total).
//
// K layout: k = 9*i + j; j=0: silu(x_i), j=1..8: cubic B-spline bases.
// Chunk: 16 features = 144 k = 9 k16 steps. 304-B smem row stride
// (stride mod 128 = 48 -> 8-row ldmatrix spans disjoint, conflict-free).

#define N_IN   256
#define KTOT   2304
#define CHUNKS 16
#define CK     144
#define KSTEPS 9
#define ROWB   304
#define ABUF   (64 * ROWB)             // 19456
#define BBUF   (256 * ROWB)            // 77824
#define DYN_SMEM (2 * ABUF + 2 * BBUF) // 194560
#define NROWS  32768

__device__ __align__(128) __half g_Wh[N_IN * KTOT];          // [out][k]
__device__ __align__(128) __half g_A[(size_t)NROWS * KTOT];  // [row][k] scratch

// ---- helpers --------------------------------------------------------------
__device__ __forceinline__ uint32_t smem_u32(const void* p) {
    uint32_t a;
    asm("{ .reg .u64 t; cvta.to.shared.u64 t, %1; cvt.u32.u64 %0, t; }" : "=r"(a) : "l"(p));
    return a;
}
__device__ __forceinline__ void cp16(uint32_t dst, const void* src) {
    asm volatile("cp.async.cg.shared.global [%0], [%1], 16;" :: "r"(dst), "l"(src) : "memory");
}
__device__ __forceinline__ void cp_commit() {
    asm volatile("cp.async.commit_group;" ::: "memory");
}
template <int N>
__device__ __forceinline__ void cp_wait() {
    asm volatile("cp.async.wait_group %0;" :: "n"(N) : "memory");
}
__device__ __forceinline__ void ldm_x4(uint32_t& r0, uint32_t& r1, uint32_t& r2, uint32_t& r3,
                                       uint32_t addr) {
    asm volatile("ldmatrix.sync.aligned.m8n8.x4.shared.b16 {%0,%1,%2,%3}, [%4];"
                 : "=r"(r0), "=r"(r1), "=r"(r2), "=r"(r3) : "r"(addr));
}
__device__ __forceinline__ void mma16816(float& c0, float& c1, float& c2, float& c3,
                                         uint32_t a0, uint32_t a1, uint32_t a2, uint32_t a3,
                                         uint32_t b0, uint32_t b1) {
    asm volatile(
        "mma.sync.aligned.m16n8k16.row.col.f32.f16.f16.f32 "
        "{%0,%1,%2,%3}, {%4,%5,%6,%7}, {%8,%9}, {%0,%1,%2,%3};"
        : "+f"(c0), "+f"(c1), "+f"(c2), "+f"(c3)
        : "r"(a0), "r"(a1), "r"(a2), "r"(a3), "r"(b0), "r"(b1));
}

// ---- cubic B-spline bases on grid -2.2 + 0.4j (Cox-de-Boor) ---------------
__device__ __forceinline__ void compute_bases(float x, float b[8]) {
    const float h = 0.4f;
    float t[11];
#pragma unroll
    for (int i = 0; i < 11; i++) {
        float gl = -2.2f + i * h;
        t[i] = (x >= gl && x < gl + h) ? 1.0f : 0.0f;
    }
#pragma unroll
    for (int i = 0; i < 10; i++) {
        float gi = -2.2f + i * h;
        t[i] = (x - gi) * 2.5f * t[i] + ((gi + 2.f * h) - x) * 2.5f * t[i + 1];
    }
#pragma unroll
    for (int i = 0; i < 9; i++) {
        float gi = -2.2f + i * h;
        t[i] = (x - gi) * 1.25f * t[i] + ((gi + 3.f * h) - x) * 1.25f * t[i + 1];
    }
#pragma unroll
    for (int i = 0; i < 8; i++) {
        float gi = -2.2f + i * h;
        b[i] = (x - gi) * (2.5f / 3.f) * t[i] + ((gi + 4.f * h) - x) * (2.5f / 3.f) * t[i + 1];
    }
}

// ---- weight repack to fp16 [out][k] ---------------------------------------
__global__ void repack_kernel(const float* __restrict__ baseW,
                              const float* __restrict__ splineW) {
    int idx = blockIdx.x * blockDim.x + threadIdx.x;
    if (idx >= N_IN * KTOT) return;
    int o = idx / KTOT, k = idx % KTOT;
    int i = k / 9, j = k % 9;
    float v = (j == 0) ? baseW[o * N_IN + i] : splineW[o * (N_IN * 8) + i * 8 + (j - 1)];
    g_Wh[idx] = __float2half_rn(v);
}

// ---- A generation: one thread = one (row, 8-feature octet) ----------------
__global__ __launch_bounds__(256)
void gen_kernel(const float* __restrict__ x) {
    int idx = blockIdx.x * blockDim.x + threadIdx.x;   // 0 .. 32768*32-1
    int row = idx >> 5;
    int oct = idx & 31;                                // features oct*8..+7
    const float* xp = x + (size_t)row * N_IN + oct * 8;
    float4 xa = *reinterpret_cast<const float4*>(xp);
    float4 xb = *reinterpret_cast<const float4*>(xp + 4);
    float xv[8] = {xa.x, xa.y, xa.z, xa.w, xb.x, xb.y, xb.z, xb.w};
    uint32_t pk[36];
#pragma unroll
    for (int i = 0; i < 36; i++) pk[i] = 0u;
#pragma unroll
    for (int f = 0; f < 8; f++) {
        float v = xv[f];
        float sil = v / (1.f + __expf(-v));
        float bs[8];
        compute_bases(v, bs);
        unsigned short hh[9];
        hh[0] = __half_as_ushort(__float2half_rn(sil));
#pragma unroll
        for (int j = 0; j < 8; j++) hh[j + 1] = __half_as_ushort(__float2half_rn(bs[j]));
#pragma unroll
        for (int j = 0; j < 9; j++) {
            int pos = 9 * f + j;
            pk[pos >> 1] |= (uint32_t)hh[j] << ((pos & 1) * 16);
        }
    }
    unsigned char* dst = reinterpret_cast<unsigned char*>(g_A)
                       + (size_t)row * (KTOT * 2) + oct * 144;
#pragma unroll
    for (int q = 0; q < 9; q++) {
        uint4 v = make_uint4(pk[4 * q], pk[4 * q + 1], pk[4 * q + 2], pk[4 * q + 3]);
        *reinterpret_cast<uint4*>(dst + q * 16) = v;
    }
}

// ---- pure GEMM kernel: 64x256 tile, 32x64 warp tiles, full double-buffer ---
__global__ __launch_bounds__(256, 1)
void gemm_kernel(float* __restrict__ out) {
    extern __shared__ __align__(128) unsigned char dsm[];   // A0 A1 B0 B1
    const uint32_t sb = smem_u32(dsm);
    const int tid = threadIdx.x, wid = tid >> 5, lane = tid & 31;
    const int row0 = blockIdx.x * 64;

    // warp tiling: 2 (m) x 4 (n); warp tile 32 rows x 64 cols
    const int wm = wid & 1;
    const int wn = wid >> 1;
    const uint32_t a_off = (uint32_t)(wm * 32 + (lane & 15)) * ROWB + ((lane >> 4) << 3) * 2;
    const uint32_t b_off = (uint32_t)(wn * 64 + ((lane >> 4) << 3) + (lane & 7)) * ROWB
                         + (((lane >> 3) & 1) << 3) * 2;

    float C[2][8][4];                          // [mt][n8][frag] = 64 regs
#pragma unroll
    for (int a = 0; a < 2; a++)
#pragma unroll
        for (int b = 0; b < 8; b++)
#pragma unroll
            for (int c = 0; c < 4; c++) C[a][b][c] = 0.f;

    // combined stage for chunk c into buffer set `buf` (ONE commit group)
    auto stage = [&](int c, int buf) {
        // A: 64 rows x 18 segs of 16B = 1152 segs
        const unsigned char* asrc = reinterpret_cast<const unsigned char*>(g_A)
                                  + (size_t)row0 * (KTOT * 2) + c * (CK * 2);
        uint32_t adst = sb + (uint32_t)buf * ABUF;
#pragma unroll
        for (int s = 0; s < 5; s++) {
            int e = tid + 256 * s;
            if (e < 1152) {
                int n = e / 18, seg = e % 18;
                cp16(adst + (uint32_t)n * ROWB + seg * 16,
                     asrc + (size_t)n * (KTOT * 2) + seg * 16);
            }
        }
        // B: 256 rows x 18 segs of 16B = 4608 segs
        const __half* bsrc = g_Wh + c * CK;
        uint32_t bdst = sb + 2 * ABUF + (uint32_t)buf * BBUF;
#pragma unroll
        for (int s = 0; s < 18; s++) {
            int e = tid + 256 * s;
            int n = e / 18, seg = e % 18;
            cp16(bdst + (uint32_t)n * ROWB + seg * 16,
                 bsrc + (size_t)n * KTOT + seg * 8);
        }
        cp_commit();
    };

    // prologue: G0, G1 in flight; wait<1> -> G0 resident
    stage(0, 0);
    stage(1, 1);
    cp_wait<1>();
    __syncthreads();

    for (int c = 0; c < CHUNKS; c++) {
        const int buf = c & 1;
        const uint32_t abase = sb + (uint32_t)buf * ABUF;
        const uint32_t bbase = sb + 2 * ABUF + (uint32_t)buf * BBUF;

#pragma unroll
        for (int s = 0; s < KSTEPS; s++) {
            const uint32_t kb = (uint32_t)(s * 16) * 2;
            uint32_t A[2][4], B[4][4];
#pragma unroll
            for (int mt = 0; mt < 2; mt++)
                ldm_x4(A[mt][0], A[mt][1], A[mt][2], A[mt][3],
                       abase + a_off + (uint32_t)mt * (16 * ROWB) + kb);
#pragma unroll
            for (int nt = 0; nt < 4; nt++)
                ldm_x4(B[nt][0], B[nt][1], B[nt][2], B[nt][3],
                       bbase + b_off + (uint32_t)nt * (16 * ROWB) + kb);
#pragma unroll
            for (int mt = 0; mt < 2; mt++)
#pragma unroll
                for (int nt = 0; nt < 4; nt++) {
                    mma16816(C[mt][2 * nt][0], C[mt][2 * nt][1],
                             C[mt][2 * nt][2], C[mt][2 * nt][3],
                             A[mt][0], A[mt][1], A[mt][2], A[mt][3],
                             B[nt][0], B[nt][1]);
                    mma16816(C[mt][2 * nt + 1][0], C[mt][2 * nt + 1][1],
                             C[mt][2 * nt + 1][2], C[mt][2 * nt + 1][3],
                             A[mt][0], A[mt][1], A[mt][2], A[mt][3],
                             B[nt][2], B[nt][3]);
                }
        }

        __syncthreads();                       // reads of buffer set `buf` done
        if (c + 2 < CHUNKS) {
            stage(c + 2, buf);                 // refill freed set, 2 ahead
            cp_wait<1>();                      // retires G(c+1): landed during MMA
        } else {
            cp_wait<0>();
        }
        __syncthreads();
    }

    // epilogue
    const int crow = lane >> 2, ccol = (lane & 3) * 2;
#pragma unroll
    for (int mt = 0; mt < 2; mt++) {
        int r = row0 + wm * 32 + mt * 16 + crow;
#pragma unroll
        for (int n8 = 0; n8 < 8; n8++) {
            int cc = wn * 64 + n8 * 8 + ccol;
            *reinterpret_cast<float2*>(out + (size_t)r * 256 + cc) =
                make_float2(C[mt][n8][0], C[mt][n8][1]);
            *reinterpret_cast<float2*>(out + (size_t)(r + 8) * 256 + cc) =
                make_float2(C[mt][n8][2], C[mt][n8][3]);
        }
    }
}

// ---- launch ---------------------------------------------------------------
extern "C" void kernel_launch(void* const* d_in, const int* in_sizes, int n_in,
                              void* d_out, int out_size) {
    const float* x       = (const float*)d_in[0];
    const float* baseW   = (const float*)d_in[1];
    const float* splineW = (const float*)d_in[2];
    float* out           = (float*)d_out;
    const int n_rows = in_sizes[0] / N_IN;            // 32768

    repack_kernel<<<(N_IN * KTOT + 255) / 256, 256>>>(baseW, splineW);
    gen_kernel<<<(n_rows * 32) / 256, 256>>>(x);

    cudaFuncSetAttribute(gemm_kernel, cudaFuncAttributeMaxDynamicSharedMemorySize, DYN_SMEM);
    gemm_kernel<<<n_rows / 64, 256, DYN_SMEM>>>(out);
}